// round 1
// baseline (speedup 1.0000x reference)
#include <cuda_runtime.h>
#include <cuda_bf16.h>

// Problem constants (fixed by the dataset)
#define B_  8
#define S_  4096
#define D_  1024
#define H_  16
#define HD_ 64
#define NR_ 32
#define ROWS_ (B_ * S_ * H_)        // 524288
#define RPB 128                      // rows per block
#define PITCH 65                     // smem row pitch (65 mod 32 == 1 -> conflict-free column access)

// Device scratch (static allocation only — harness forbids cudaMalloc)
__device__ float g_cos_tab[S_ * NR_];
__device__ float g_sin_tab[S_ * NR_];
__device__ float g_rc[NR_];
__device__ float g_rs[NR_];
__device__ int   g_ri[NR_];
__device__ int   g_rj[NR_];
__device__ int   g_identity;

// ---------------------------------------------------------------------------
// Setup: rotation params + r_matrix identity check
// ---------------------------------------------------------------------------
__global__ void setup_kernel(const float* __restrict__ thetas,
                             const float* __restrict__ r_pairs,
                             const float* __restrict__ theta_scale,
                             const float* __restrict__ r_matrix) {
    int t = threadIdx.x;   // 64 threads
    if (t < NR_) {
        float th = thetas[t] * theta_scale[0];
        float sv, cv;
        sincosf(th, &sv, &cv);
        g_rc[t] = cv;
        g_rs[t] = sv;
        int i = (int)r_pairs[2 * t];       // truncation toward zero == astype(int32) for positives
        int j = (int)r_pairs[2 * t + 1];
        if (i < 0) i = 0; if (i > HD_ - 1) i = HD_ - 1;
        if (j < 0) j = 0; if (j > HD_ - 1) j = HD_ - 1;
        g_ri[t] = i;
        g_rj[t] = j;
    }
    // identity check: thread t scans row t of r_matrix (exact compare — input is jnp.eye)
    int ok = 1;
    for (int c = 0; c < HD_; c++) {
        float v = r_matrix[t * HD_ + c];
        ok &= (v == ((t == c) ? 1.0f : 0.0f));
    }
    __shared__ int sh_ok;
    if (t == 0) sh_ok = 1;
    __syncthreads();
    if (!ok) atomicAnd(&sh_ok, 0);
    __syncthreads();
    if (t == 0) g_identity = sh_ok;
}

// ---------------------------------------------------------------------------
// Precompute sin/cos RoPE table: [S_][NR_]
// ---------------------------------------------------------------------------
__global__ void table_kernel(const float* __restrict__ inv_freq) {
    int idx = blockIdx.x * blockDim.x + threadIdx.x;
    if (idx < S_ * NR_) {
        int s = idx >> 5;       // / NR_
        int k = idx & (NR_ - 1);
        float a = (float)s * inv_freq[k];
        float sv, cv;
        sincosf(a, &sv, &cv);
        g_sin_tab[idx] = sv;
        g_cos_tab[idx] = cv;
    }
}

// ---------------------------------------------------------------------------
// Main: per-row Givens chain (+ optional dense r_matrix) + RoPE remix
// ---------------------------------------------------------------------------
__global__ __launch_bounds__(RPB)
void rotary_main_kernel(const float* __restrict__ x,
                        const float* __restrict__ r_matrix,
                        float* __restrict__ out) {
    __shared__ float sm[RPB * PITCH];
    __shared__ float sc[NR_], ss[NR_];
    __shared__ int   si[NR_], sj[NR_];

    const int t = threadIdx.x;
    const long long block_row0 = (long long)blockIdx.x * RPB;
    const float4* __restrict__ x4 = (const float4*)(x + block_row0 * HD_);
    float4* __restrict__ o4 = (float4*)(out + block_row0 * HD_);

    if (t < NR_) {
        sc[t] = g_rc[t]; ss[t] = g_rs[t];
        si[t] = g_ri[t]; sj[t] = g_rj[t];
    }

    // ---- load 128x64 floats (2048 float4, fully coalesced) into padded smem
    #pragma unroll
    for (int it = 0; it < 16; it++) {
        int q = t + it * RPB;           // float4 index in [0, 2048)
        float4 v = x4[q];
        int r = q >> 4;                  // q*4 / 64
        int c = (q & 15) * 4;
        float* p = &sm[r * PITCH + c];
        p[0] = v.x; p[1] = v.y; p[2] = v.z; p[3] = v.w;
    }
    __syncthreads();

    // ---- per-row sequential Givens rotations (thread t owns row t)
    float* row = &sm[t * PITCH];
    #pragma unroll 1
    for (int k = 0; k < NR_; k++) {
        int i = si[k], j = sj[k];
        float c = sc[k], s = ss[k];
        float xi = row[i];
        float xj = row[j];
        if (i == j) {
            row[i] = xi * c;
        } else {
            row[i] = xi * c + xj * s;
            row[j] = xj * c - xi * s;
        }
    }

    // ---- general path: dense multiply by r_matrix (never taken when r_matrix == I)
    if (!g_identity) {
        float y[HD_];
        for (int c2 = 0; c2 < HD_; c2++) {
            float acc = 0.0f;
            for (int k = 0; k < HD_; k++)
                acc = fmaf(row[k], __ldg(&r_matrix[k * HD_ + c2]), acc);
            y[c2] = acc;
        }
        for (int c2 = 0; c2 < HD_; c2++) row[c2] = y[c2];
    }

    // ---- RoPE remix: out[k] = y[2k]*cos - y[2k+1]*sin ; out[k+32] = y[2k]*sin + y[2k+1]*cos
    {
        int s_pos = (int)(((block_row0 + t) >> 4) & (S_ - 1));  // (row / H) % S
        const float* __restrict__ ct = &g_cos_tab[s_pos * NR_];
        const float* __restrict__ st = &g_sin_tab[s_pos * NR_];

        // save upper half before it gets overwritten (breaks in-place hazard)
        float ysave[32];
        #pragma unroll
        for (int k = 0; k < 32; k++) ysave[k] = row[32 + k];

        #pragma unroll
        for (int k = 0; k < 16; k++) {
            float cv = ct[k], sv = st[k];
            float a = row[2 * k];
            float b = row[2 * k + 1];
            row[k]      = a * cv - b * sv;
            row[k + 32] = a * sv + b * cv;
        }
        #pragma unroll
        for (int k = 16; k < 32; k++) {
            float cv = ct[k], sv = st[k];
            float a = ysave[2 * k - 32];
            float b = ysave[2 * k - 31];
            row[k]      = a * cv - b * sv;
            row[k + 32] = a * sv + b * cv;
        }
    }
    __syncthreads();

    // ---- coalesced float4 store
    #pragma unroll
    for (int it = 0; it < 16; it++) {
        int q = t + it * RPB;
        int r = q >> 4;
        int c = (q & 15) * 4;
        const float* p = &sm[r * PITCH + c];
        float4 v;
        v.x = p[0]; v.y = p[1]; v.z = p[2]; v.w = p[3];
        o4[q] = v;
    }
}

// ---------------------------------------------------------------------------
extern "C" void kernel_launch(void* const* d_in, const int* in_sizes, int n_in,
                              void* d_out, int out_size) {
    const float* x           = (const float*)d_in[0];
    const float* thetas      = (const float*)d_in[1];
    const float* r_pairs     = (const float*)d_in[2];
    const float* theta_scale = (const float*)d_in[3];
    // d_in[4] = n_rots_scale (unused by reference)
    const float* r_matrix    = (const float*)d_in[5];
    const float* inv_freq    = (const float*)d_in[6];
    float* out = (float*)d_out;

    setup_kernel<<<1, 64>>>(thetas, r_pairs, theta_scale, r_matrix);
    table_kernel<<<(S_ * NR_ + 255) / 256, 256>>>(inv_freq);
    rotary_main_kernel<<<ROWS_ / RPB, RPB>>>(x, r_matrix, out);
}

// round 2
// speedup vs baseline: 1.1880x; 1.1880x over previous
#include <cuda_runtime.h>
#include <cuda_bf16.h>

// Problem constants (fixed by the dataset)
#define B_  8
#define S_  4096
#define D_  1024
#define H_  16
#define HD_ 64
#define NR_ 32
#define ROWS_ (B_ * S_ * H_)        // 524288
#define RPB 128                      // rows per block
#define PITCH 65                     // smem row pitch (odd -> conflict-free column access)

// Device scratch (static allocation only — harness forbids cudaMalloc)
__device__ float g_cos_tab[S_ * NR_];
__device__ float g_sin_tab[S_ * NR_];
__device__ float g_rc[NR_];
__device__ float g_rs[NR_];
__device__ int   g_ri[NR_];
__device__ int   g_rj[NR_];
__device__ int   g_identity;

// ---------------------------------------------------------------------------
// Fused prep: RoPE sin/cos table (all blocks) + rotation params & identity
// check (block 0 only). Identity scan is unrolled 16-wide for MLP.
// ---------------------------------------------------------------------------
__global__ __launch_bounds__(256)
void prep_kernel(const float* __restrict__ thetas,
                 const float* __restrict__ r_pairs,
                 const float* __restrict__ theta_scale,
                 const float* __restrict__ inv_freq,
                 const float* __restrict__ r_matrix) {
    int idx = blockIdx.x * 256 + threadIdx.x;
    if (idx < S_ * NR_) {
        int s = idx >> 5;
        int k = idx & (NR_ - 1);
        float a = (float)s * inv_freq[k];
        float sv, cv;
        sincosf(a, &sv, &cv);
        g_sin_tab[idx] = sv;
        g_cos_tab[idx] = cv;
    }

    if (blockIdx.x == 0) {
        int t = threadIdx.x;
        if (t < NR_) {
            float th = thetas[t] * theta_scale[0];
            float sv, cv;
            sincosf(th, &sv, &cv);
            g_rc[t] = cv;
            g_rs[t] = sv;
            int i = (int)r_pairs[2 * t];
            int j = (int)r_pairs[2 * t + 1];
            if (i < 0) i = 0; if (i > HD_ - 1) i = HD_ - 1;
            if (j < 0) j = 0; if (j > HD_ - 1) j = HD_ - 1;
            g_ri[t] = i;
            g_rj[t] = j;
        }
        // identity check: 4096 elements, 16 per thread, unrolled (MLP=16)
        int ok = 1;
        #pragma unroll
        for (int k = 0; k < 16; k++) {
            int e = t * 16 + k;
            float v = r_matrix[e];
            float want = ((e >> 6) == (e & 63)) ? 1.0f : 0.0f;
            ok &= (v == want);
        }
        ok = __all_sync(0xffffffffu, ok);
        __shared__ int w_ok[8];
        if ((t & 31) == 0) w_ok[t >> 5] = ok;
        __syncthreads();
        if (t == 0) {
            int a = 1;
            #pragma unroll
            for (int w = 0; w < 8; w++) a &= w_ok[w];
            g_identity = a;
        }
    }
}

// ---------------------------------------------------------------------------
// Main: per-row Givens chain (+ optional dense r_matrix) with RoPE remix
// fused into the coalesced stage-out.
// ---------------------------------------------------------------------------
__global__ __launch_bounds__(RPB)
void rotary_main_kernel(const float* __restrict__ x,
                        const float* __restrict__ r_matrix,
                        float* __restrict__ out) {
    __shared__ float sm[RPB * PITCH];
    __shared__ float s_cos[8 * NR_];     // 8 s-positions per block
    __shared__ float s_sin[8 * NR_];
    __shared__ float sc[NR_], ss[NR_];
    __shared__ int   si[NR_], sj[NR_];

    const int t = threadIdx.x;
    const long long block_row0 = (long long)blockIdx.x * RPB;
    const float4* __restrict__ x4 = (const float4*)(x + block_row0 * HD_);
    float4* __restrict__ o4 = (float4*)(out + block_row0 * HD_);

    if (t < NR_) {
        sc[t] = g_rc[t]; ss[t] = g_rs[t];
        si[t] = g_ri[t]; sj[t] = g_rj[t];
    }
    // stage RoPE table slice: rows span 8 consecutive s-positions
    {
        int s0 = (int)((block_row0 >> 4) & (S_ - 1));   // row/16 mod S == s
        int base = s0 * NR_;
        s_cos[t]       = g_cos_tab[base + t];
        s_cos[t + 128] = g_cos_tab[base + 128 + t];
        s_sin[t]       = g_sin_tab[base + t];
        s_sin[t + 128] = g_sin_tab[base + 128 + t];
    }

    // ---- load 128x64 floats (2048 float4, fully coalesced) into padded smem
    #pragma unroll
    for (int it = 0; it < 16; it++) {
        int q = t + it * RPB;           // float4 index in [0, 2048)
        float4 v = x4[q];
        int r = q >> 4;
        int c = (q & 15) * 4;
        float* p = &sm[r * PITCH + c];
        p[0] = v.x; p[1] = v.y; p[2] = v.z; p[3] = v.w;
    }
    __syncthreads();

    // ---- per-row sequential Givens rotations (thread t owns row t)
    {
        float* row = &sm[t * PITCH];
        #pragma unroll 1
        for (int k = 0; k < NR_; k++) {
            int i = si[k], j = sj[k];
            float c = sc[k], s = ss[k];
            float xi = row[i];
            float xj = row[j];
            if (i == j) {
                row[i] = xi * c;
            } else {
                row[i] = xi * c + xj * s;
                row[j] = xj * c - xi * s;
            }
        }

        // general path: dense multiply by r_matrix (not taken when r_matrix == I)
        if (!g_identity) {
            float y[HD_];
            for (int c2 = 0; c2 < HD_; c2++) {
                float acc = 0.0f;
                for (int k = 0; k < HD_; k++)
                    acc = fmaf(row[k], __ldg(&r_matrix[k * HD_ + c2]), acc);
                y[c2] = acc;
            }
            for (int c2 = 0; c2 < HD_; c2++) row[c2] = y[c2];
        }
    }
    __syncthreads();

    // ---- fused RoPE remix + coalesced float4 stage-out
    // Thread's output column group is fixed: cc = (t&15)*4. Rows visited are
    // r = (t>>4) + it*8; grouped by s-position g = r>>4 so cos/sin vectors are
    // loaded once per g (aligned LDS.128) and reused for 2 rows.
    {
        const int cc    = (t & 15) * 4;       // output col base, 0..60
        const bool hi   = cc >= 32;           // second half -> sin branch
        const int c2    = hi ? cc - 32 : cc;  // table/phase column
        const int rbase = t >> 4;             // 0..7

        #pragma unroll
        for (int g = 0; g < 8; g++) {
            float4 cv = *(const float4*)&s_cos[g * NR_ + c2];
            float4 sv = *(const float4*)&s_sin[g * NR_ + c2];
            #pragma unroll
            for (int h = 0; h < 2; h++) {
                int r = 16 * g + rbase + h * 8;
                const float* row = &sm[r * PITCH];
                // pre-remix values y[2*c2 .. 2*c2+7]
                float a0 = row[2 * c2 + 0], b0 = row[2 * c2 + 1];
                float a1 = row[2 * c2 + 2], b1 = row[2 * c2 + 3];
                float a2 = row[2 * c2 + 4], b2 = row[2 * c2 + 5];
                float a3 = row[2 * c2 + 6], b3 = row[2 * c2 + 7];
                float4 o;
                if (!hi) {
                    o.x = a0 * cv.x - b0 * sv.x;
                    o.y = a1 * cv.y - b1 * sv.y;
                    o.z = a2 * cv.z - b2 * sv.z;
                    o.w = a3 * cv.w - b3 * sv.w;
                } else {
                    o.x = a0 * sv.x + b0 * cv.x;
                    o.y = a1 * sv.y + b1 * cv.y;
                    o.z = a2 * sv.z + b2 * cv.z;
                    o.w = a3 * sv.w + b3 * cv.w;
                }
                o4[r * 16 + (t & 15)] = o;
            }
        }
    }
}

// ---------------------------------------------------------------------------
extern "C" void kernel_launch(void* const* d_in, const int* in_sizes, int n_in,
                              void* d_out, int out_size) {
    const float* x           = (const float*)d_in[0];
    const float* thetas      = (const float*)d_in[1];
    const float* r_pairs     = (const float*)d_in[2];
    const float* theta_scale = (const float*)d_in[3];
    // d_in[4] = n_rots_scale (unused by reference)
    const float* r_matrix    = (const float*)d_in[5];
    const float* inv_freq    = (const float*)d_in[6];
    float* out = (float*)d_out;

    prep_kernel<<<(S_ * NR_ + 255) / 256, 256>>>(thetas, r_pairs, theta_scale,
                                                 inv_freq, r_matrix);
    rotary_main_kernel<<<ROWS_ / RPB, RPB>>>(x, r_matrix, out);
}

// round 3
// speedup vs baseline: 1.4563x; 1.2258x over previous
#include <cuda_runtime.h>
#include <cuda_bf16.h>

// Problem constants (fixed by the dataset)
#define B_  8
#define S_  4096
#define D_  1024
#define H_  16
#define HD_ 64
#define NR_ 32
#define ROWS_ (B_ * S_ * H_)        // 524288
#define RPB 128                      // rows per block
#define PITCH 69                     // 69 mod 32 == 5 (odd) -> conflict-free uniform-column access

// column permutation: upper half shifted by 4 banks
__device__ __forceinline__ int col_perm(int c) { return c + ((c >= 32) ? 4 : 0); }

// ---------------------------------------------------------------------------
// Single fused kernel: per-block param prep + Givens chain + RoPE remix.
// ---------------------------------------------------------------------------
__global__ __launch_bounds__(RPB)
void rotary_fused_kernel(const float* __restrict__ x,
                         const float* __restrict__ thetas,
                         const float* __restrict__ r_pairs,
                         const float* __restrict__ theta_scale,
                         const float* __restrict__ inv_freq,
                         const float* __restrict__ r_matrix,
                         float* __restrict__ out) {
    __shared__ float sm[RPB * PITCH];
    __shared__ __align__(16) float s_cos[8 * NR_];   // 8 s-positions x 32 freqs
    __shared__ __align__(16) float s_sin[8 * NR_];
    __shared__ float sc[NR_], ss[NR_];
    __shared__ int   si[NR_], sj[NR_];
    __shared__ int   w_ok[4];

    const int t = threadIdx.x;
    const long long block_row0 = (long long)blockIdx.x * RPB;
    const float4* __restrict__ x4 = (const float4*)(x + block_row0 * HD_);
    float4* __restrict__ o4 = (float4*)(out + block_row0 * HD_);

    // ---- stage-in: 128x64 floats, coalesced float4 LDG -> permuted smem
    #pragma unroll
    for (int it = 0; it < 16; it++) {
        int q = t + it * RPB;           // float4 index in [0, 2048)
        float4 v = x4[q];
        int r = q >> 4;
        int c = (q & 15) * 4;
        float* p = &sm[r * PITCH + col_perm(c)];
        p[0] = v.x; p[1] = v.y; p[2] = v.z; p[3] = v.w;
    }

    // ---- per-block rotation params (threads 0..31)
    if (t < NR_) {
        float th = thetas[t] * theta_scale[0];
        float sv, cv;
        sincosf(th, &sv, &cv);
        sc[t] = cv;
        ss[t] = sv;
        int i = (int)r_pairs[2 * t];
        int j = (int)r_pairs[2 * t + 1];
        if (i < 0) i = 0; if (i > HD_ - 1) i = HD_ - 1;
        if (j < 0) j = 0; if (j > HD_ - 1) j = HD_ - 1;
        si[t] = col_perm(i);
        sj[t] = col_perm(j);
    }

    // ---- per-block RoPE table slice: 8 consecutive s-positions (rows/16)
    {
        int s0 = (int)((block_row0 >> 4) & (S_ - 1));
        #pragma unroll
        for (int u = 0; u < 2; u++) {
            int idx = t + u * RPB;          // 0..255
            int g = idx >> 5;
            int k = idx & (NR_ - 1);
            float a = (float)(s0 + g) * inv_freq[k];
            float sv, cv;
            sincosf(a, &sv, &cv);
            s_cos[idx] = cv;
            s_sin[idx] = sv;
        }
    }

    // ---- per-block identity check on r_matrix (coalesced float4, 8/thread)
    {
        const float4* rm4 = (const float4*)r_matrix;
        int ok = 1;
        #pragma unroll
        for (int k = 0; k < 8; k++) {
            int q = k * RPB + t;            // float4 idx in [0,1024)
            float4 v = rm4[q];
            int e = q * 4;
            ok &= (v.x == (((e + 0) >> 6) == ((e + 0) & 63) ? 1.0f : 0.0f));
            ok &= (v.y == (((e + 1) >> 6) == ((e + 1) & 63) ? 1.0f : 0.0f));
            ok &= (v.z == (((e + 2) >> 6) == ((e + 2) & 63) ? 1.0f : 0.0f));
            ok &= (v.w == (((e + 3) >> 6) == ((e + 3) & 63) ? 1.0f : 0.0f));
        }
        ok = __all_sync(0xffffffffu, ok);
        if ((t & 31) == 0) w_ok[t >> 5] = ok;
    }
    __syncthreads();

    const int identity = w_ok[0] & w_ok[1] & w_ok[2] & w_ok[3];

    // ---- per-row sequential Givens rotations (thread t owns row t)
    {
        float* row = &sm[t * PITCH];
        #pragma unroll 1
        for (int k = 0; k < NR_; k++) {
            int i = si[k], j = sj[k];
            float c = sc[k], s = ss[k];
            float xi = row[i];
            float xj = row[j];
            if (i == j) {
                row[i] = xi * c;
            } else {
                row[i] = xi * c + xj * s;
                row[j] = xj * c - xi * s;
            }
        }

        // general path: dense multiply by r_matrix (not taken when r_matrix == I)
        if (!identity) {
            float y[HD_];
            for (int c2 = 0; c2 < HD_; c2++) {
                float acc = 0.0f;
                for (int k = 0; k < HD_; k++)
                    acc = fmaf(row[col_perm(k)], __ldg(&r_matrix[k * HD_ + c2]), acc);
                y[c2] = acc;
            }
            for (int c2 = 0; c2 < HD_; c2++) row[col_perm(c2)] = y[c2];
        }
    }
    __syncthreads();

    // ---- fused RoPE remix + coalesced stage-out
    // Thread (j = t&7, rslot = t>>3) computes out[4j..4j+3] AND out[4j+32..35]
    // of rows r = rslot + 16*i from ONE set of 8 y-reads (conflict-free banks).
    {
        const int j = t & 7;
        const int rslot = t >> 3;          // 0..15
        const int c0 = 8 * j;              // y columns 8j..8j+7 (never spans 32)
        const int o = col_perm(c0);

        #pragma unroll
        for (int i = 0; i < 8; i++) {
            int r = rslot + 16 * i;        // s-group == i
            float4 cv = *(const float4*)&s_cos[i * NR_ + 4 * j];
            float4 sv = *(const float4*)&s_sin[i * NR_ + 4 * j];
            const float* row = &sm[r * PITCH + o];
            float a0 = row[0], b0 = row[1];
            float a1 = row[2], b1 = row[3];
            float a2 = row[4], b2 = row[5];
            float a3 = row[6], b3 = row[7];
            float4 lo, hi;
            lo.x = a0 * cv.x - b0 * sv.x;  hi.x = a0 * sv.x + b0 * cv.x;
            lo.y = a1 * cv.y - b1 * sv.y;  hi.y = a1 * sv.y + b1 * cv.y;
            lo.z = a2 * cv.z - b2 * sv.z;  hi.z = a2 * sv.z + b2 * cv.z;
            lo.w = a3 * cv.w - b3 * sv.w;  hi.w = a3 * sv.w + b3 * cv.w;
            o4[r * 16 + j]     = lo;
            o4[r * 16 + 8 + j] = hi;
        }
    }
}

// ---------------------------------------------------------------------------
extern "C" void kernel_launch(void* const* d_in, const int* in_sizes, int n_in,
                              void* d_out, int out_size) {
    const float* x           = (const float*)d_in[0];
    const float* thetas      = (const float*)d_in[1];
    const float* r_pairs     = (const float*)d_in[2];
    const float* theta_scale = (const float*)d_in[3];
    // d_in[4] = n_rots_scale (unused by reference)
    const float* r_matrix    = (const float*)d_in[5];
    const float* inv_freq    = (const float*)d_in[6];
    float* out = (float*)d_out;

    rotary_fused_kernel<<<ROWS_ / RPB, RPB>>>(x, thetas, r_pairs, theta_scale,
                                              inv_freq, r_matrix, out);
}